// round 1
// baseline (speedup 1.0000x reference)
#include <cuda_runtime.h>
#include <cuda_bf16.h>
#include <math.h>

// Problem constants (fixed-shape problem)
#define BATCH 4
#define SEQ   2048
#define FEATS 1024
#define HEADS 16
#define HDIM  64
#define TOKENS (BATCH * SEQ)          // 8192
#define NSPLIT 8                       // split-K for KtV

// ---------------------------------------------------------------------------
// Scratch (device globals; no allocation allowed)
// ---------------------------------------------------------------------------
__device__ float g_Q[TOKENS * FEATS];
__device__ float g_K[TOKENS * FEATS];
__device__ float g_V[TOKENS * FEATS];
__device__ float g_O[TOKENS * FEATS];
__device__ float g_Mpart[NSPLIT * BATCH * HEADS * HDIM * HDIM];  // [split][bh][i][j]
__device__ float g_M[BATCH * HEADS * HDIM * HDIM];               // [bh][i][j]

// ---------------------------------------------------------------------------
// SGEMM: C[M,N] = A[M,K] @ B[K,N] + bias[N]   (all row-major, fp32)
// BM=BN=128, BK=16, 256 threads, 8x8 per thread.
// ---------------------------------------------------------------------------
#define BM 128
#define BN 128
#define BK 16
#define TM 8
#define TN 8

__global__ __launch_bounds__(256, 2)
void sgemm_bias_kernel(const float* __restrict__ A, const float* __restrict__ B,
                       const float* __restrict__ bias, float* __restrict__ C,
                       int M, int N, int K)
{
    __shared__ float As[BK][BM + 4];   // padded: reduces store conflicts
    __shared__ float Bs[BK][BN];

    const int tid  = threadIdx.x;
    const int tx   = tid & 15;         // 0..15  (N direction)
    const int ty   = tid >> 4;         // 0..15  (M direction)

    const float* Ab = A + (size_t)blockIdx.y * BM * K;
    const float* Bb = B + (size_t)blockIdx.x * BN;

    float acc[TM][TN];
    #pragma unroll
    for (int i = 0; i < TM; i++)
        #pragma unroll
        for (int j = 0; j < TN; j++) acc[i][j] = 0.0f;

    for (int k0 = 0; k0 < K; k0 += BK) {
        // ---- load A tile [BM x BK], stored transposed into As[k][m]
        #pragma unroll
        for (int l = 0; l < 2; l++) {
            int i    = tid + l * 256;          // float4 id, 0..511
            int row  = i >> 2;                 // 0..127
            int col4 = (i & 3) * 4;            // 0,4,8,12
            float4 v = *(const float4*)(Ab + (size_t)row * K + k0 + col4);
            As[col4 + 0][row] = v.x;
            As[col4 + 1][row] = v.y;
            As[col4 + 2][row] = v.z;
            As[col4 + 3][row] = v.w;
        }
        // ---- load B tile [BK x BN]
        #pragma unroll
        for (int l = 0; l < 2; l++) {
            int i    = tid + l * 256;          // float4 id, 0..511
            int row  = i >> 5;                 // 0..15
            int col4 = (i & 31) * 4;           // 0..124
            *(float4*)(&Bs[row][col4]) =
                *(const float4*)(Bb + (size_t)(k0 + row) * N + col4);
        }
        __syncthreads();

        #pragma unroll
        for (int kk = 0; kk < BK; kk++) {
            float a[TM], b[TN];
            float4 a0 = *(const float4*)(&As[kk][ty * TM]);
            float4 a1 = *(const float4*)(&As[kk][ty * TM + 4]);
            a[0]=a0.x; a[1]=a0.y; a[2]=a0.z; a[3]=a0.w;
            a[4]=a1.x; a[5]=a1.y; a[6]=a1.z; a[7]=a1.w;
            float4 b0 = *(const float4*)(&Bs[kk][tx * TN]);
            float4 b1 = *(const float4*)(&Bs[kk][tx * TN + 4]);
            b[0]=b0.x; b[1]=b0.y; b[2]=b0.z; b[3]=b0.w;
            b[4]=b1.x; b[5]=b1.y; b[6]=b1.z; b[7]=b1.w;
            #pragma unroll
            for (int i = 0; i < TM; i++)
                #pragma unroll
                for (int j = 0; j < TN; j++)
                    acc[i][j] = fmaf(a[i], b[j], acc[i][j]);
        }
        __syncthreads();
    }

    // ---- epilogue: add bias, store
    #pragma unroll
    for (int i = 0; i < TM; i++) {
        int r = blockIdx.y * BM + ty * TM + i;
        #pragma unroll
        for (int j = 0; j < TN; j += 4) {
            int c = blockIdx.x * BN + tx * TN + j;
            float4 o;
            o.x = acc[i][j + 0] + bias[c + 0];
            o.y = acc[i][j + 1] + bias[c + 1];
            o.z = acc[i][j + 2] + bias[c + 2];
            o.w = acc[i][j + 3] + bias[c + 3];
            *(float4*)(C + (size_t)r * N + c) = o;
        }
    }
}

// ---------------------------------------------------------------------------
// Per-head L2 normalize in place: buf rows are [token][HEADS*HDIM];
// normalize each 64-wide head segment.  One warp per (token, head).
// ---------------------------------------------------------------------------
__global__ void l2norm_kernel(float* __restrict__ buf)
{
    int gw   = (blockIdx.x * blockDim.x + threadIdx.x) >> 5;
    int lane = threadIdx.x & 31;
    const int total = TOKENS * HEADS;
    if (gw >= total) return;
    float* p = buf + (size_t)(gw >> 4) * FEATS + (gw & 15) * HDIM;
    float2 v = *(float2*)(p + lane * 2);
    float ss = v.x * v.x + v.y * v.y;
    #pragma unroll
    for (int o = 16; o; o >>= 1) ss += __shfl_xor_sync(0xffffffff, ss, o);
    float inv = 1.0f / fmaxf(sqrtf(ss), 1e-12f);
    v.x *= inv; v.y *= inv;
    *(float2*)(p + lane * 2) = v;
}

// ---------------------------------------------------------------------------
// KtV partials: for each (b,h), split s: Mpart[s][bh] = K_bh[s-chunk]^T @ V_bh[s-chunk]
// grid = (64 bh, NSPLIT), block = 256 (16x16 threads, 4x4 per thread over 64x64)
// ---------------------------------------------------------------------------
__global__ void ktv_kernel(const float* __restrict__ Kbuf, const float* __restrict__ Vbuf)
{
    const int bh = blockIdx.x;           // 0..63
    const int s  = blockIdx.y;           // 0..NSPLIT-1
    const int b  = bh >> 4, h = bh & 15;
    const float* Kb = Kbuf + (size_t)b * SEQ * FEATS + h * HDIM;
    const float* Vb = Vbuf + (size_t)b * SEQ * FEATS + h * HDIM;

    __shared__ float Ks[32][64];
    __shared__ float Vs[32][64];

    const int tid = threadIdx.x;
    const int ti  = tid >> 4;            // 0..15
    const int tj  = tid & 15;            // 0..15

    float acc[4][4];
    #pragma unroll
    for (int a = 0; a < 4; a++)
        #pragma unroll
        for (int c = 0; c < 4; c++) acc[a][c] = 0.0f;

    const int tokens_per_split = SEQ / NSPLIT;   // 256
    for (int t0 = s * tokens_per_split; t0 < (s + 1) * tokens_per_split; t0 += 32) {
        #pragma unroll
        for (int l = 0; l < 2; l++) {
            int i   = tid + l * 256;             // float4 id, 0..511
            int row = i >> 4;                    // 0..31
            int col = (i & 15) * 4;              // 0..60
            *(float4*)&Ks[row][col] = *(const float4*)(Kb + (size_t)(t0 + row) * FEATS + col);
            *(float4*)&Vs[row][col] = *(const float4*)(Vb + (size_t)(t0 + row) * FEATS + col);
        }
        __syncthreads();
        #pragma unroll
        for (int tt = 0; tt < 32; tt++) {
            float4 kv = *(const float4*)&Ks[tt][ti * 4];
            float4 vv = *(const float4*)&Vs[tt][tj * 4];
            float ka[4] = {kv.x, kv.y, kv.z, kv.w};
            float va[4] = {vv.x, vv.y, vv.z, vv.w};
            #pragma unroll
            for (int a = 0; a < 4; a++)
                #pragma unroll
                for (int c = 0; c < 4; c++)
                    acc[a][c] = fmaf(ka[a], va[c], acc[a][c]);
        }
        __syncthreads();
    }

    float* out = g_Mpart + ((size_t)s * 64 + bh) * HDIM * HDIM;
    #pragma unroll
    for (int a = 0; a < 4; a++)
        #pragma unroll
        for (int c = 0; c < 4; c++)
            out[(ti * 4 + a) * HDIM + (tj * 4 + c)] = acc[a][c];
}

// Deterministic fixed-order reduction of split partials.
__global__ void reduce_m_kernel()
{
    int i = blockIdx.x * blockDim.x + threadIdx.x;
    const int per = 64 * HDIM * HDIM;    // 262144
    if (i >= per) return;
    float sum = 0.0f;
    #pragma unroll
    for (int p = 0; p < NSPLIT; p++) sum += g_Mpart[(size_t)p * per + i];
    g_M[i] = sum;
}

// ---------------------------------------------------------------------------
// O = Q @ M / n^sigmoid(m_h)  per (b,h). grid = (SEQ/32, 64 bh), block = 256.
// Each thread: 1 token (32 per block), 8 output dims.
// ---------------------------------------------------------------------------
__global__ void qm_kernel(const float* __restrict__ Qbuf, const float* __restrict__ m,
                          float* __restrict__ Obuf)
{
    const int bh = blockIdx.y;
    const int b  = bh >> 4, h = bh & 15;
    const int t0 = blockIdx.x * 32;

    __shared__ float Ms[64][64];
    __shared__ float Qs[32][68];         // padded for conflict-free reads

    const int tid = threadIdx.x;

    // per-head scale: 1 / n^{sigmoid(m_h)}
    float sig   = 1.0f / (1.0f + expf(-m[h]));
    float inv_s = powf((float)SEQ, -sig);

    const float* Mp = g_M + (size_t)bh * HDIM * HDIM;
    for (int i = tid; i < HDIM * HDIM; i += 256)
        ((float*)Ms)[ (i >> 6) * 64 + (i & 63) ] = Mp[i] * inv_s;

    const float* Qb = Qbuf + (size_t)(b * SEQ + t0) * FEATS + h * HDIM;
    #pragma unroll
    for (int l = 0; l < 2; l++) {
        int i   = tid + l * 256;         // float4 id, 0..511
        int row = i >> 4;                // 0..31
        int col = (i & 15) * 4;          // 0..60
        *(float4*)&Qs[row][col] = *(const float4*)(Qb + (size_t)row * FEATS + col);
    }
    __syncthreads();

    const int tl = tid >> 3;             // token within tile, 0..31
    const int j0 = (tid & 7) * 8;        // output dim group

    float acc[8];
    #pragma unroll
    for (int j = 0; j < 8; j++) acc[j] = 0.0f;

    #pragma unroll
    for (int i = 0; i < HDIM; i++) {
        float q  = Qs[tl][i];
        float4 m0 = *(const float4*)&Ms[i][j0];
        float4 m1 = *(const float4*)&Ms[i][j0 + 4];
        acc[0] = fmaf(q, m0.x, acc[0]);
        acc[1] = fmaf(q, m0.y, acc[1]);
        acc[2] = fmaf(q, m0.z, acc[2]);
        acc[3] = fmaf(q, m0.w, acc[3]);
        acc[4] = fmaf(q, m1.x, acc[4]);
        acc[5] = fmaf(q, m1.y, acc[5]);
        acc[6] = fmaf(q, m1.z, acc[6]);
        acc[7] = fmaf(q, m1.w, acc[7]);
    }

    float* Ob = Obuf + (size_t)(b * SEQ + t0 + tl) * FEATS + h * HDIM + j0;
    *(float4*)Ob       = make_float4(acc[0], acc[1], acc[2], acc[3]);
    *(float4*)(Ob + 4) = make_float4(acc[4], acc[5], acc[6], acc[7]);
}

// ---------------------------------------------------------------------------
// Launch
// ---------------------------------------------------------------------------
extern "C" void kernel_launch(void* const* d_in, const int* in_sizes, int n_in,
                              void* d_out, int out_size)
{
    const float* x  = (const float*)d_in[0];
    const float* Wq = (const float*)d_in[1];
    const float* bq = (const float*)d_in[2];
    const float* Wk = (const float*)d_in[3];
    const float* bk = (const float*)d_in[4];
    const float* Wv = (const float*)d_in[5];
    const float* bv = (const float*)d_in[6];
    const float* Wo = (const float*)d_in[7];
    const float* bo = (const float*)d_in[8];
    const float* m  = (const float*)d_in[9];
    float* out = (float*)d_out;

    void *pQ, *pK, *pV, *pO;
    cudaGetSymbolAddress(&pQ, g_Q);
    cudaGetSymbolAddress(&pK, g_K);
    cudaGetSymbolAddress(&pV, g_V);
    cudaGetSymbolAddress(&pO, g_O);
    float* Qb = (float*)pQ;
    float* Kb = (float*)pK;
    float* Vb = (float*)pV;
    float* Ob = (float*)pO;

    dim3 gGemm(FEATS / BN, TOKENS / BM);   // (8, 64)
    // Projections
    sgemm_bias_kernel<<<gGemm, 256>>>(x, Wq, bq, Qb, TOKENS, FEATS, FEATS);
    sgemm_bias_kernel<<<gGemm, 256>>>(x, Wk, bk, Kb, TOKENS, FEATS, FEATS);
    sgemm_bias_kernel<<<gGemm, 256>>>(x, Wv, bv, Vb, TOKENS, FEATS, FEATS);

    // L2 normalize Q and K per head
    int nwarps  = TOKENS * HEADS;                    // 131072
    int nblocks = (nwarps * 32 + 255) / 256;         // 16384
    l2norm_kernel<<<nblocks, 256>>>(Qb);
    l2norm_kernel<<<nblocks, 256>>>(Kb);

    // KtV (split-K, deterministic reduction)
    ktv_kernel<<<dim3(BATCH * HEADS, NSPLIT), 256>>>(Kb, Vb);
    reduce_m_kernel<<<(64 * HDIM * HDIM + 255) / 256, 256>>>();

    // O = Q @ M / scale
    qm_kernel<<<dim3(SEQ / 32, BATCH * HEADS), 256>>>(Qb, m, Ob);

    // Output projection
    sgemm_bias_kernel<<<gGemm, 256>>>(Ob, Wo, bo, out, TOKENS, FEATS, FEATS);
}

// round 4
// speedup vs baseline: 2.2080x; 2.2080x over previous
#include <cuda_runtime.h>
#include <cuda_bf16.h>
#include <math.h>
#include <stdint.h>

// Problem constants
#define BATCH 4
#define SEQ   2048
#define FEATS 1024
#define HEADS 16
#define HDIM  64
#define TOKENS (BATCH * SEQ)          // 8192
#define NSPLIT 8

// ---------------------------------------------------------------------------
// Scratch (device globals; no allocation allowed)
// ---------------------------------------------------------------------------
__device__ float g_Q[TOKENS * FEATS];
__device__ float g_K[TOKENS * FEATS];
__device__ float g_V[TOKENS * FEATS];
__device__ float g_Mpart[NSPLIT * 64 * HDIM * HDIM];
__device__ float g_M[64 * HDIM * HDIM];
__device__ __nv_bfloat16 g_WtH[4u * FEATS * FEATS];   // transposed weights, bf16 hi
__device__ __nv_bfloat16 g_WtL[4u * FEATS * FEATS];   // transposed weights, bf16 lo
__device__ __nv_bfloat16 g_Xh[TOKENS * FEATS];        // x split hi
__device__ __nv_bfloat16 g_Xl[TOKENS * FEATS];        // x split lo
__device__ __nv_bfloat16 g_Oh[TOKENS * FEATS];        // attention out hi
__device__ __nv_bfloat16 g_Ol[TOKENS * FEATS];        // attention out lo

// ---------------------------------------------------------------------------
// PTX helpers (sm_100-safe: mma.sync + ldmatrix + cp.async only)
// ---------------------------------------------------------------------------
__device__ __forceinline__ uint32_t smem_u32(const void* p) {
    uint32_t a;
    asm("{ .reg .u64 t; cvta.to.shared.u64 t, %1; cvt.u32.u64 %0, t; }"
        : "=r"(a) : "l"(p));
    return a;
}

#define CP16(dst, src) \
    asm volatile("cp.async.cg.shared.global [%0], [%1], 16;" \
                 :: "r"(dst), "l"(src) : "memory")
#define CP_COMMIT() asm volatile("cp.async.commit_group;" ::: "memory")
#define CP_WAIT1()  asm volatile("cp.async.wait_group 1;" ::: "memory")
#define CP_WAIT0()  asm volatile("cp.async.wait_group 0;" ::: "memory")

#define LDSM_X4(r0, r1, r2, r3, addr) \
    asm volatile("ldmatrix.sync.aligned.m8n8.x4.shared.b16 {%0,%1,%2,%3}, [%4];" \
                 : "=r"(r0), "=r"(r1), "=r"(r2), "=r"(r3) : "r"(addr))

#define MMA_BF16(d, a, b0, b1) \
    asm volatile("mma.sync.aligned.m16n8k16.row.col.f32.bf16.bf16.f32 " \
                 "{%0,%1,%2,%3}, {%4,%5,%6,%7}, {%8,%9}, {%0,%1,%2,%3};" \
                 : "+f"((d)[0]), "+f"((d)[1]), "+f"((d)[2]), "+f"((d)[3]) \
                 : "r"((a)[0]), "r"((a)[1]), "r"((a)[2]), "r"((a)[3]), \
                   "r"(b0), "r"(b1))

__device__ __forceinline__ uint32_t packbf(float a, float b) {
    uint32_t lo = (uint32_t)__bfloat16_as_ushort(__float2bfloat16_rn(a));
    uint32_t hi = (uint32_t)__bfloat16_as_ushort(__float2bfloat16_rn(b));
    return lo | (hi << 16);
}

// ---------------------------------------------------------------------------
// prep_w: W[K,N] fp32 -> Wt[N,K] bf16 hi/lo  (4 weight matrices)
// ---------------------------------------------------------------------------
__global__ void prep_w_kernel(const float* __restrict__ W0, const float* __restrict__ W1,
                              const float* __restrict__ W2, const float* __restrict__ W3)
{
    __shared__ float t[32][33];
    const int z = blockIdx.z;
    const float* W = (z == 0) ? W0 : (z == 1) ? W1 : (z == 2) ? W2 : W3;
    __nv_bfloat16* Hp = g_WtH + (size_t)z * FEATS * FEATS;
    __nv_bfloat16* Lp = g_WtL + (size_t)z * FEATS * FEATS;
    const int n0 = blockIdx.x * 32, k0 = blockIdx.y * 32;
    const int tid = threadIdx.x;
    const int a = tid & 31, bq = tid >> 5;
    #pragma unroll
    for (int it = 0; it < 4; it++) {
        int kk = bq + it * 8;
        t[kk][a] = W[(size_t)(k0 + kk) * FEATS + n0 + a];
    }
    __syncthreads();
    #pragma unroll
    for (int it = 0; it < 4; it++) {
        int nn = bq + it * 8;
        float v = t[a][nn];
        __nv_bfloat16 h = __float2bfloat16_rn(v);
        __nv_bfloat16 l = __float2bfloat16_rn(v - __bfloat162float(h));
        size_t o = (size_t)(n0 + nn) * FEATS + k0 + a;
        Hp[o] = h;
        Lp[o] = l;
    }
}

// ---------------------------------------------------------------------------
// prep_x: x fp32 -> bf16 hi/lo
// ---------------------------------------------------------------------------
__global__ void prep_x_kernel(const float* __restrict__ X)
{
    size_t i = (size_t)blockIdx.x * 256 + threadIdx.x;   // float4 index
    float4 v = ((const float4*)X)[i];
    __nv_bfloat16 h0 = __float2bfloat16_rn(v.x);
    __nv_bfloat16 h1 = __float2bfloat16_rn(v.y);
    __nv_bfloat16 h2 = __float2bfloat16_rn(v.z);
    __nv_bfloat16 h3 = __float2bfloat16_rn(v.w);
    uint2 hp, lp;
    hp.x = (uint32_t)__bfloat16_as_ushort(h0) | ((uint32_t)__bfloat16_as_ushort(h1) << 16);
    hp.y = (uint32_t)__bfloat16_as_ushort(h2) | ((uint32_t)__bfloat16_as_ushort(h3) << 16);
    lp.x = packbf(v.x - __bfloat162float(h0), v.y - __bfloat162float(h1));
    lp.y = packbf(v.z - __bfloat162float(h2), v.w - __bfloat162float(h3));
    ((uint2*)g_Xh)[i] = hp;
    ((uint2*)g_Xl)[i] = lp;
}

// ---------------------------------------------------------------------------
// bf16x3 mma.sync GEMM:  C[8192,1024] = (AH+AL) @ (BH+BL)^T + bias
// A: [M,K] bf16 hi/lo   B: [N,K] bf16 hi/lo   C fp32
// Tile 128x128x64, 8 warps (4x2), warp tile 32x64, 3-stage cp.async pipeline.
// do_norm: fuse per-head (64-col) L2 normalization into epilogue.
// ---------------------------------------------------------------------------
#define GBK 64
#define NCHUNK (FEATS / GBK)           // 16
#define TILE_B 16384                   // one 128x64 bf16 tile
#define STAGE_B (4 * TILE_B)           // 65536
#define OFF_AH 0
#define OFF_AL TILE_B
#define OFF_BH (2 * TILE_B)
#define OFF_BL (3 * TILE_B)
#define GEMM_SMEM (3 * STAGE_B)        // 196608

__device__ __forceinline__ void gemm_issue(uint32_t st, int tid,
    const __nv_bfloat16* __restrict__ AH, const __nv_bfloat16* __restrict__ AL,
    const __nv_bfloat16* __restrict__ BH, const __nv_bfloat16* __restrict__ BL,
    int m0, int n0, int k0)
{
    const uint32_t sah = st + OFF_AH, sal = st + OFF_AL;
    const uint32_t sbh = st + OFF_BH, sbl = st + OFF_BL;
    #pragma unroll
    for (int t = 0; t < 4; t++) {
        const int i  = tid + t * 256;   // 0..1023
        const int r  = i >> 3;          // 0..127
        const int ch = i & 7;           // 16B chunk within 128B row
        const uint32_t d = (uint32_t)(r * 128 + ((ch ^ (r & 7)) << 4));
        const size_t ga = (size_t)(m0 + r) * FEATS + k0 + ch * 8;
        const size_t gb = (size_t)(n0 + r) * FEATS + k0 + ch * 8;
        CP16(sah + d, AH + ga);
        CP16(sal + d, AL + ga);
        CP16(sbh + d, BH + gb);
        CP16(sbl + d, BL + gb);
    }
    CP_COMMIT();
}

__global__ __launch_bounds__(256, 1)
void gemm_kernel(const __nv_bfloat16* __restrict__ AH, const __nv_bfloat16* __restrict__ AL,
                 const __nv_bfloat16* __restrict__ BH, const __nv_bfloat16* __restrict__ BL,
                 const float* __restrict__ bias, float* __restrict__ C, int do_norm)
{
    extern __shared__ char smem[];
    const uint32_t sb = smem_u32(smem);
    const int tid  = threadIdx.x;
    const int lane = tid & 31;
    const int warp = tid >> 5;
    const int wm   = warp & 3;         // 0..3 (M)
    const int wn   = warp >> 2;        // 0..1 (N)
    const int m0 = blockIdx.y * 128;
    const int n0 = blockIdx.x * 128;

    float acc[2][8][4];
    #pragma unroll
    for (int a = 0; a < 2; a++)
        #pragma unroll
        for (int j = 0; j < 8; j++)
            #pragma unroll
            for (int k = 0; k < 4; k++) acc[a][j][k] = 0.0f;

    // prologue: stages 0, 1
    gemm_issue(sb + 0 * STAGE_B, tid, AH, AL, BH, BL, m0, n0, 0);
    gemm_issue(sb + 1 * STAGE_B, tid, AH, AL, BH, BL, m0, n0, GBK);

    for (int c = 0; c < NCHUNK; c++) {
        if (c + 2 < NCHUNK) CP_WAIT1(); else CP_WAIT0();
        __syncthreads();
        if (c + 2 < NCHUNK)
            gemm_issue(sb + ((c + 2) % 3) * STAGE_B, tid, AH, AL, BH, BL,
                       m0, n0, (c + 2) * GBK);

        const uint32_t st = sb + (c % 3) * STAGE_B;
        #pragma unroll
        for (int s = 0; s < 4; s++) {     // k16 steps within 64-chunk
            const int chl = s * 2 + (lane >> 4);
            uint32_t ah[2][4], al[2][4];
            #pragma unroll
            for (int a = 0; a < 2; a++) {
                int row = wm * 32 + a * 16 + (lane & 15);
                uint32_t off = (uint32_t)(row * 128 + ((chl ^ (row & 7)) << 4));
                LDSM_X4(ah[a][0], ah[a][1], ah[a][2], ah[a][3], st + OFF_AH + off);
                LDSM_X4(al[a][0], al[a][1], al[a][2], al[a][3], st + OFF_AL + off);
            }
            uint32_t bh[4][4], bl[4][4];
            #pragma unroll
            for (int p = 0; p < 4; p++) {
                int row = wn * 64 + p * 16 + (lane & 15);
                uint32_t off = (uint32_t)(row * 128 + ((chl ^ (row & 7)) << 4));
                LDSM_X4(bh[p][0], bh[p][1], bh[p][2], bh[p][3], st + OFF_BH + off);
                LDSM_X4(bl[p][0], bl[p][1], bl[p][2], bl[p][3], st + OFF_BL + off);
            }
            #pragma unroll
            for (int a = 0; a < 2; a++)
                #pragma unroll
                for (int j = 0; j < 8; j++) {
                    const int p = j >> 1, q = j & 1;
                    MMA_BF16(acc[a][j], ah[a], bh[p][q], bh[p][q + 2]);
                    MMA_BF16(acc[a][j], al[a], bh[p][q], bh[p][q + 2]);
                    MMA_BF16(acc[a][j], ah[a], bl[p][q], bl[p][q + 2]);
                }
        }
    }

    // ---- epilogue: +bias, optional per-head L2 norm (warp n-span = 1 head) ----
    float2 bv[8];
    #pragma unroll
    for (int j = 0; j < 8; j++)
        bv[j] = *(const float2*)&bias[n0 + wn * 64 + j * 8 + (lane & 3) * 2];
    #pragma unroll
    for (int a = 0; a < 2; a++)
        #pragma unroll
        for (int j = 0; j < 8; j++) {
            acc[a][j][0] += bv[j].x;
            acc[a][j][1] += bv[j].y;
            acc[a][j][2] += bv[j].x;
            acc[a][j][3] += bv[j].y;
        }

    float inv[2][2] = {{1.0f, 1.0f}, {1.0f, 1.0f}};
    if (do_norm) {
        #pragma unroll
        for (int a = 0; a < 2; a++) {
            float s0 = 0.0f, s1 = 0.0f;
            #pragma unroll
            for (int j = 0; j < 8; j++) {
                s0 += acc[a][j][0] * acc[a][j][0] + acc[a][j][1] * acc[a][j][1];
                s1 += acc[a][j][2] * acc[a][j][2] + acc[a][j][3] * acc[a][j][3];
            }
            s0 += __shfl_xor_sync(0xffffffff, s0, 1);
            s0 += __shfl_xor_sync(0xffffffff, s0, 2);
            s1 += __shfl_xor_sync(0xffffffff, s1, 1);
            s1 += __shfl_xor_sync(0xffffffff, s1, 2);
            inv[a][0] = 1.0f / fmaxf(sqrtf(s0), 1e-12f);
            inv[a][1] = 1.0f / fmaxf(sqrtf(s1), 1e-12f);
        }
    }

    #pragma unroll
    for (int a = 0; a < 2; a++) {
        int row = m0 + wm * 32 + a * 16 + (lane >> 2);
        #pragma unroll
        for (int j = 0; j < 8; j++) {
            int col = n0 + wn * 64 + j * 8 + (lane & 3) * 2;
            *(float2*)&C[(size_t)row * FEATS + col] =
                make_float2(acc[a][j][0] * inv[a][0], acc[a][j][1] * inv[a][0]);
            *(float2*)&C[(size_t)(row + 8) * FEATS + col] =
                make_float2(acc[a][j][2] * inv[a][1], acc[a][j][3] * inv[a][1]);
        }
    }
}

// ---------------------------------------------------------------------------
// KtV partials
// ---------------------------------------------------------------------------
__global__ void ktv_kernel(const float* __restrict__ Kbuf, const float* __restrict__ Vbuf)
{
    const int bh = blockIdx.x;
    const int s  = blockIdx.y;
    const int b  = bh >> 4, h = bh & 15;
    const float* Kb = Kbuf + (size_t)b * SEQ * FEATS + h * HDIM;
    const float* Vb = Vbuf + (size_t)b * SEQ * FEATS + h * HDIM;

    __shared__ float Ks[32][64];
    __shared__ float Vs[32][64];

    const int tid = threadIdx.x;
    const int ti  = tid >> 4;
    const int tj  = tid & 15;

    float acc[4][4];
    #pragma unroll
    for (int a = 0; a < 4; a++)
        #pragma unroll
        for (int c = 0; c < 4; c++) acc[a][c] = 0.0f;

    const int tokens_per_split = SEQ / NSPLIT;
    for (int t0 = s * tokens_per_split; t0 < (s + 1) * tokens_per_split; t0 += 32) {
        #pragma unroll
        for (int l2 = 0; l2 < 2; l2++) {
            int i   = tid + l2 * 256;
            int row = i >> 4;
            int col = (i & 15) * 4;
            *(float4*)&Ks[row][col] = *(const float4*)(Kb + (size_t)(t0 + row) * FEATS + col);
            *(float4*)&Vs[row][col] = *(const float4*)(Vb + (size_t)(t0 + row) * FEATS + col);
        }
        __syncthreads();
        #pragma unroll
        for (int tt = 0; tt < 32; tt++) {
            float4 kv = *(const float4*)&Ks[tt][ti * 4];
            float4 vv = *(const float4*)&Vs[tt][tj * 4];
            float ka[4] = {kv.x, kv.y, kv.z, kv.w};
            float va[4] = {vv.x, vv.y, vv.z, vv.w};
            #pragma unroll
            for (int a = 0; a < 4; a++)
                #pragma unroll
                for (int c = 0; c < 4; c++)
                    acc[a][c] = fmaf(ka[a], va[c], acc[a][c]);
        }
        __syncthreads();
    }

    float* out = g_Mpart + ((size_t)s * 64 + bh) * HDIM * HDIM;
    #pragma unroll
    for (int a = 0; a < 4; a++)
        #pragma unroll
        for (int c = 0; c < 4; c++)
            out[(ti * 4 + a) * HDIM + (tj * 4 + c)] = acc[a][c];
}

__global__ void reduce_m_kernel()
{
    int i = blockIdx.x * blockDim.x + threadIdx.x;
    const int per = 64 * HDIM * HDIM;
    if (i >= per) return;
    float sum = 0.0f;
    #pragma unroll
    for (int p = 0; p < NSPLIT; p++) sum += g_Mpart[(size_t)p * per + i];
    g_M[i] = sum;
}

// ---------------------------------------------------------------------------
// O = Q @ M / n^sigmoid(m_h), written as bf16 hi/lo for the final GEMM.
// ---------------------------------------------------------------------------
__global__ void qm_kernel(const float* __restrict__ Qbuf, const float* __restrict__ m)
{
    const int bh = blockIdx.y;
    const int b  = bh >> 4, h = bh & 15;
    const int t0 = blockIdx.x * 32;

    __shared__ float Ms[64][64];
    __shared__ float Qs[32][68];

    const int tid = threadIdx.x;

    float sig   = 1.0f / (1.0f + expf(-m[h]));
    float inv_s = powf((float)SEQ, -sig);

    const float* Mp = g_M + (size_t)bh * HDIM * HDIM;
    for (int i = tid; i < HDIM * HDIM; i += 256)
        ((float*)Ms)[(i >> 6) * 64 + (i & 63)] = Mp[i] * inv_s;

    const float* Qb = Qbuf + (size_t)(b * SEQ + t0) * FEATS + h * HDIM;
    #pragma unroll
    for (int l2 = 0; l2 < 2; l2++) {
        int i   = tid + l2 * 256;
        int row = i >> 4;
        int col = (i & 15) * 4;
        *(float4*)&Qs[row][col] = *(const float4*)(Qb + (size_t)row * FEATS + col);
    }
    __syncthreads();

    const int tl = tid >> 3;
    const int j0 = (tid & 7) * 8;

    float acc[8];
    #pragma unroll
    for (int j = 0; j < 8; j++) acc[j] = 0.0f;

    #pragma unroll
    for (int i = 0; i < HDIM; i++) {
        float q  = Qs[tl][i];
        float4 m0 = *(const float4*)&Ms[i][j0];
        float4 m1 = *(const float4*)&Ms[i][j0 + 4];
        acc[0] = fmaf(q, m0.x, acc[0]);
        acc[1] = fmaf(q, m0.y, acc[1]);
        acc[2] = fmaf(q, m0.z, acc[2]);
        acc[3] = fmaf(q, m0.w, acc[3]);
        acc[4] = fmaf(q, m1.x, acc[4]);
        acc[5] = fmaf(q, m1.y, acc[5]);
        acc[6] = fmaf(q, m1.z, acc[6]);
        acc[7] = fmaf(q, m1.w, acc[7]);
    }

    // split to bf16 hi/lo and store packed (8 bf16 = 16B each)
    uint32_t hv[4], lv[4];
    #pragma unroll
    for (int q4 = 0; q4 < 4; q4++) {
        float x0 = acc[q4 * 2], x1 = acc[q4 * 2 + 1];
        __nv_bfloat16 h0 = __float2bfloat16_rn(x0);
        __nv_bfloat16 h1 = __float2bfloat16_rn(x1);
        hv[q4] = (uint32_t)__bfloat16_as_ushort(h0) | ((uint32_t)__bfloat16_as_ushort(h1) << 16);
        lv[q4] = packbf(x0 - __bfloat162float(h0), x1 - __bfloat162float(h1));
    }
    size_t off = (size_t)(b * SEQ + t0 + tl) * FEATS + h * HDIM + j0;
    *(uint4*)((char*)g_Oh + off * 2) = make_uint4(hv[0], hv[1], hv[2], hv[3]);
    *(uint4*)((char*)g_Ol + off * 2) = make_uint4(lv[0], lv[1], lv[2], lv[3]);
}

// ---------------------------------------------------------------------------
// Launch
// ---------------------------------------------------------------------------
extern "C" void kernel_launch(void* const* d_in, const int* in_sizes, int n_in,
                              void* d_out, int out_size)
{
    const float* x  = (const float*)d_in[0];
    const float* Wq = (const float*)d_in[1];
    const float* bq = (const float*)d_in[2];
    const float* Wk = (const float*)d_in[3];
    const float* bk = (const float*)d_in[4];
    const float* Wv = (const float*)d_in[5];
    const float* bv = (const float*)d_in[6];
    const float* Wo = (const float*)d_in[7];
    const float* bo = (const float*)d_in[8];
    const float* m  = (const float*)d_in[9];
    float* out = (float*)d_out;

    void *pQ, *pK, *pV, *pWH, *pWL, *pXh, *pXl, *pOh, *pOl;
    cudaGetSymbolAddress(&pQ, g_Q);
    cudaGetSymbolAddress(&pK, g_K);
    cudaGetSymbolAddress(&pV, g_V);
    cudaGetSymbolAddress(&pWH, g_WtH);
    cudaGetSymbolAddress(&pWL, g_WtL);
    cudaGetSymbolAddress(&pXh, g_Xh);
    cudaGetSymbolAddress(&pXl, g_Xl);
    cudaGetSymbolAddress(&pOh, g_Oh);
    cudaGetSymbolAddress(&pOl, g_Ol);
    float* Qb = (float*)pQ;
    float* Kb = (float*)pK;
    float* Vb = (float*)pV;
    const __nv_bfloat16* WH = (const __nv_bfloat16*)pWH;
    const __nv_bfloat16* WL = (const __nv_bfloat16*)pWL;
    const __nv_bfloat16* Xh = (const __nv_bfloat16*)pXh;
    const __nv_bfloat16* Xl = (const __nv_bfloat16*)pXl;
    const __nv_bfloat16* Oh = (const __nv_bfloat16*)pOh;
    const __nv_bfloat16* Ol = (const __nv_bfloat16*)pOl;
    const size_t FF = (size_t)FEATS * FEATS;

    cudaFuncSetAttribute(gemm_kernel, cudaFuncAttributeMaxDynamicSharedMemorySize,
                         GEMM_SMEM);

    // 1. Split inputs to bf16 hi/lo
    prep_w_kernel<<<dim3(32, 32, 4), 256>>>(Wq, Wk, Wv, Wo);
    prep_x_kernel<<<TOKENS * FEATS / 4 / 256, 256>>>(x);

    // 2. Projections via mma.sync bf16x3 (Q/K with fused per-head L2 norm)
    dim3 gGemm(FEATS / 128, TOKENS / 128);   // (8, 64)
    gemm_kernel<<<gGemm, 256, GEMM_SMEM>>>(Xh, Xl, WH + 0 * FF, WL + 0 * FF, bq, Qb, 1);
    gemm_kernel<<<gGemm, 256, GEMM_SMEM>>>(Xh, Xl, WH + 1 * FF, WL + 1 * FF, bk, Kb, 1);
    gemm_kernel<<<gGemm, 256, GEMM_SMEM>>>(Xh, Xl, WH + 2 * FF, WL + 2 * FF, bv, Vb, 0);

    // 3. Linear attention: M = K^T V, O = Q M / n^sigmoid(m)
    ktv_kernel<<<dim3(64, NSPLIT), 256>>>(Kb, Vb);
    reduce_m_kernel<<<(64 * HDIM * HDIM + 255) / 256, 256>>>();
    qm_kernel<<<dim3(SEQ / 32, 64), 256>>>(Qb, m);

    // 4. Output projection
    gemm_kernel<<<gGemm, 256, GEMM_SMEM>>>(Oh, Ol, WH + 3 * FF, WL + 3 * FF, bo, out, 0);
}

// round 6
// speedup vs baseline: 3.0528x; 1.3826x over previous
#include <cuda_runtime.h>
#include <cuda_bf16.h>
#include <cuda_fp16.h>
#include <math.h>
#include <stdint.h>

// Problem constants
#define BATCH 4
#define SEQ   2048
#define FEATS 1024
#define HEADS 16
#define HDIM  64
#define TOKENS (BATCH * SEQ)          // 8192
#define NSPLIT 8

// Weight pre-scale (keeps fp16 lo parts normal); epilogue divides it out.
#define WSCALE     64.0f
#define INV_WSCALE 0.015625f

// ---------------------------------------------------------------------------
// Scratch (device globals; no allocation allowed)
// ---------------------------------------------------------------------------
__device__ float g_Q[TOKENS * FEATS];
__device__ float g_K[TOKENS * FEATS];
__device__ float g_V[TOKENS * FEATS];
__device__ float g_Mpart[NSPLIT * 64 * HDIM * HDIM];
__device__ float g_M[64 * HDIM * HDIM];
__device__ __half g_WtH[4u * FEATS * FEATS];   // transposed weights *64, fp16 hi
__device__ __half g_WtL[4u * FEATS * FEATS];   // transposed weights *64, fp16 lo
__device__ __half g_Xh[TOKENS * FEATS];        // x as fp16
__device__ __half g_Ox[TOKENS * FEATS];        // attention out as fp16

// ---------------------------------------------------------------------------
// PTX helpers (sm_100-safe: mma.sync + ldmatrix + cp.async only)
// ---------------------------------------------------------------------------
__device__ __forceinline__ uint32_t smem_u32(const void* p) {
    uint32_t a;
    asm("{ .reg .u64 t; cvta.to.shared.u64 t, %1; cvt.u32.u64 %0, t; }"
        : "=r"(a) : "l"(p));
    return a;
}

#define CP16(dst, src) \
    asm volatile("cp.async.cg.shared.global [%0], [%1], 16;" \
                 :: "r"(dst), "l"(src) : "memory")
#define CP_COMMIT() asm volatile("cp.async.commit_group;" ::: "memory")
#define CP_WAIT1()  asm volatile("cp.async.wait_group 1;" ::: "memory")
#define CP_WAIT0()  asm volatile("cp.async.wait_group 0;" ::: "memory")

#define LDSM_X4(r0, r1, r2, r3, addr) \
    asm volatile("ldmatrix.sync.aligned.m8n8.x4.shared.b16 {%0,%1,%2,%3}, [%4];" \
                 : "=r"(r0), "=r"(r1), "=r"(r2), "=r"(r3) : "r"(addr))

#define MMA_F16(d, a, b0, b1) \
    asm volatile("mma.sync.aligned.m16n8k16.row.col.f32.f16.f16.f32 " \
                 "{%0,%1,%2,%3}, {%4,%5,%6,%7}, {%8,%9}, {%0,%1,%2,%3};" \
                 : "+f"((d)[0]), "+f"((d)[1]), "+f"((d)[2]), "+f"((d)[3]) \
                 : "r"((a)[0]), "r"((a)[1]), "r"((a)[2]), "r"((a)[3]), \
                   "r"(b0), "r"(b1))

// ---------------------------------------------------------------------------
// prep_w: W[K,N] fp32 -> Wt[N,K] fp16 hi/lo of (W * WSCALE)
// ---------------------------------------------------------------------------
__global__ void prep_w_kernel(const float* __restrict__ W0, const float* __restrict__ W1,
                              const float* __restrict__ W2, const float* __restrict__ W3)
{
    __shared__ float t[32][33];
    const int z = blockIdx.z;
    const float* W = (z == 0) ? W0 : (z == 1) ? W1 : (z == 2) ? W2 : W3;
    __half* Hp = g_WtH + (size_t)z * FEATS * FEATS;
    __half* Lp = g_WtL + (size_t)z * FEATS * FEATS;
    const int n0 = blockIdx.x * 32, k0 = blockIdx.y * 32;
    const int tid = threadIdx.x;
    const int a = tid & 31, bq = tid >> 5;
    #pragma unroll
    for (int it = 0; it < 4; it++) {
        int kk = bq + it * 8;
        t[kk][a] = W[(size_t)(k0 + kk) * FEATS + n0 + a];
    }
    __syncthreads();
    #pragma unroll
    for (int it = 0; it < 4; it++) {
        int nn = bq + it * 8;
        float v = t[a][nn] * WSCALE;
        __half h = __float2half_rn(v);
        __half l = __float2half_rn(v - __half2float(h));
        size_t o = (size_t)(n0 + nn) * FEATS + k0 + a;
        Hp[o] = h;
        Lp[o] = l;
    }
}

// ---------------------------------------------------------------------------
// prep_x: x fp32 -> fp16
// ---------------------------------------------------------------------------
__global__ void prep_x_kernel(const float* __restrict__ X)
{
    size_t i = (size_t)blockIdx.x * 256 + threadIdx.x;   // float4 index
    float4 v = ((const float4*)X)[i];
    uint2 hp;
    __half2 p0 = __floats2half2_rn(v.x, v.y);
    __half2 p1 = __floats2half2_rn(v.z, v.w);
    hp.x = *(uint32_t*)&p0;
    hp.y = *(uint32_t*)&p1;
    ((uint2*)g_Xh)[i] = hp;
}

// ---------------------------------------------------------------------------
// fp16 2-pass GEMM:  C[8192,1024] = A @ (BH+BL)^T * INV_WSCALE + bias
// A: [M,K] fp16       B: [N,K] fp16 hi/lo      C fp32
// Tile 128x128x64, 8 warps (4x2), warp tile 32x64, 2-stage cp.async pipeline.
// __launch_bounds__(256,2) -> 2 CTAs/SM (96KB smem each).
// do_norm: fuse per-head (64-col) L2 normalization into epilogue.
// ---------------------------------------------------------------------------
#define GBK 64
#define NCHUNK (FEATS / GBK)           // 16
#define TILE_B 16384                   // one 128x64 fp16 tile
#define STAGE_B (3 * TILE_B)           // 49152
#define OFF_A  0
#define OFF_BH TILE_B
#define OFF_BL (2 * TILE_B)
#define GEMM_SMEM (2 * STAGE_B)        // 98304

__device__ __forceinline__ void gemm_issue(uint32_t st, int tid,
    const __half* __restrict__ A,
    const __half* __restrict__ BH, const __half* __restrict__ BL,
    int m0, int n0, int k0)
{
    const uint32_t sa  = st + OFF_A;
    const uint32_t sbh = st + OFF_BH;
    const uint32_t sbl = st + OFF_BL;
    #pragma unroll
    for (int t = 0; t < 4; t++) {
        const int i  = tid + t * 256;   // 0..1023
        const int r  = i >> 3;          // 0..127
        const int ch = i & 7;           // 16B chunk within 128B row
        const uint32_t d = (uint32_t)(r * 128 + ((ch ^ (r & 7)) << 4));
        const size_t ga = (size_t)(m0 + r) * FEATS + k0 + ch * 8;
        const size_t gb = (size_t)(n0 + r) * FEATS + k0 + ch * 8;
        CP16(sa  + d, A  + ga);
        CP16(sbh + d, BH + gb);
        CP16(sbl + d, BL + gb);
    }
    CP_COMMIT();
}

__global__ __launch_bounds__(256, 2)
void gemm_kernel(const __half* __restrict__ A,
                 const __half* __restrict__ BH, const __half* __restrict__ BL,
                 const float* __restrict__ bias, float* __restrict__ C, int do_norm)
{
    extern __shared__ char smem[];
    const uint32_t sb = smem_u32(smem);
    const int tid  = threadIdx.x;
    const int lane = tid & 31;
    const int warp = tid >> 5;
    const int wm   = warp & 3;         // 0..3 (M)
    const int wn   = warp >> 2;        // 0..1 (N)
    const int m0 = blockIdx.y * 128;
    const int n0 = blockIdx.x * 128;

    float acc[2][8][4];
    #pragma unroll
    for (int a = 0; a < 2; a++)
        #pragma unroll
        for (int j = 0; j < 8; j++)
            #pragma unroll
            for (int k = 0; k < 4; k++) acc[a][j][k] = 0.0f;

    gemm_issue(sb, tid, A, BH, BL, m0, n0, 0);

    for (int c = 0; c < NCHUNK; c++) {
        if (c + 1 < NCHUNK) {
            gemm_issue(sb + ((c + 1) & 1) * STAGE_B, tid, A, BH, BL,
                       m0, n0, (c + 1) * GBK);
            CP_WAIT1();
        } else {
            CP_WAIT0();
        }
        __syncthreads();

        const uint32_t st = sb + (c & 1) * STAGE_B;
        #pragma unroll
        for (int s = 0; s < 4; s++) {     // k16 steps within 64-chunk
            const int chl = s * 2 + (lane >> 4);
            uint32_t ah[2][4];
            #pragma unroll
            for (int a = 0; a < 2; a++) {
                int row = wm * 32 + a * 16 + (lane & 15);
                uint32_t off = (uint32_t)(row * 128 + ((chl ^ (row & 7)) << 4));
                LDSM_X4(ah[a][0], ah[a][1], ah[a][2], ah[a][3], st + OFF_A + off);
            }
            uint32_t bh[4][4], bl[4][4];
            #pragma unroll
            for (int p = 0; p < 4; p++) {
                int row = wn * 64 + p * 16 + (lane & 15);
                uint32_t off = (uint32_t)(row * 128 + ((chl ^ (row & 7)) << 4));
                LDSM_X4(bh[p][0], bh[p][1], bh[p][2], bh[p][3], st + OFF_BH + off);
                LDSM_X4(bl[p][0], bl[p][1], bl[p][2], bl[p][3], st + OFF_BL + off);
            }
            #pragma unroll
            for (int a = 0; a < 2; a++)
                #pragma unroll
                for (int j = 0; j < 8; j++) {
                    const int p = j >> 1, q = j & 1;
                    MMA_F16(acc[a][j], ah[a], bh[p][q], bh[p][q + 2]);
                    MMA_F16(acc[a][j], ah[a], bl[p][q], bl[p][q + 2]);
                }
        }
        __syncthreads();
    }

    // ---- epilogue: *1/WSCALE, +bias, optional per-head L2 norm ----
    float2 bv[8];
    #pragma unroll
    for (int j = 0; j < 8; j++)
        bv[j] = *(const float2*)&bias[n0 + wn * 64 + j * 8 + (lane & 3) * 2];
    #pragma unroll
    for (int a = 0; a < 2; a++)
        #pragma unroll
        for (int j = 0; j < 8; j++) {
            acc[a][j][0] = acc[a][j][0] * INV_WSCALE + bv[j].x;
            acc[a][j][1] = acc[a][j][1] * INV_WSCALE + bv[j].y;
            acc[a][j][2] = acc[a][j][2] * INV_WSCALE + bv[j].x;
            acc[a][j][3] = acc[a][j][3] * INV_WSCALE + bv[j].y;
        }

    float inv[2][2] = {{1.0f, 1.0f}, {1.0f, 1.0f}};
    if (do_norm) {
        #pragma unroll
        for (int a = 0; a < 2; a++) {
            float s0 = 0.0f, s1 = 0.0f;
            #pragma unroll
            for (int j = 0; j < 8; j++) {
                s0 += acc[a][j][0] * acc[a][j][0] + acc[a][j][1] * acc[a][j][1];
                s1 += acc[a][j][2] * acc[a][j][2] + acc[a][j][3] * acc[a][j][3];
            }
            s0 += __shfl_xor_sync(0xffffffff, s0, 1);
            s0 += __shfl_xor_sync(0xffffffff, s0, 2);
            s1 += __shfl_xor_sync(0xffffffff, s1, 1);
            s1 += __shfl_xor_sync(0xffffffff, s1, 2);
            inv[a][0] = 1.0f / fmaxf(sqrtf(s0), 1e-12f);
            inv[a][1] = 1.0f / fmaxf(sqrtf(s1), 1e-12f);
        }
    }

    #pragma unroll
    for (int a = 0; a < 2; a++) {
        int row = m0 + wm * 32 + a * 16 + (lane >> 2);
        #pragma unroll
        for (int j = 0; j < 8; j++) {
            int col = n0 + wn * 64 + j * 8 + (lane & 3) * 2;
            *(float2*)&C[(size_t)row * FEATS + col] =
                make_float2(acc[a][j][0] * inv[a][0], acc[a][j][1] * inv[a][0]);
            *(float2*)&C[(size_t)(row + 8) * FEATS + col] =
                make_float2(acc[a][j][2] * inv[a][1], acc[a][j][3] * inv[a][1]);
        }
    }
}

// ---------------------------------------------------------------------------
// KtV partials
// ---------------------------------------------------------------------------
__global__ void ktv_kernel(const float* __restrict__ Kbuf, const float* __restrict__ Vbuf)
{
    const int bh = blockIdx.x;
    const int s  = blockIdx.y;
    const int b  = bh >> 4, h = bh & 15;
    const float* Kb = Kbuf + (size_t)b * SEQ * FEATS + h * HDIM;
    const float* Vb = Vbuf + (size_t)b * SEQ * FEATS + h * HDIM;

    __shared__ float Ks[32][64];
    __shared__ float Vs[32][64];

    const int tid = threadIdx.x;
    const int ti  = tid >> 4;
    const int tj  = tid & 15;

    float acc[4][4];
    #pragma unroll
    for (int a = 0; a < 4; a++)
        #pragma unroll
        for (int c = 0; c < 4; c++) acc[a][c] = 0.0f;

    const int tokens_per_split = SEQ / NSPLIT;
    for (int t0 = s * tokens_per_split; t0 < (s + 1) * tokens_per_split; t0 += 32) {
        #pragma unroll
        for (int l2 = 0; l2 < 2; l2++) {
            int i   = tid + l2 * 256;
            int row = i >> 4;
            int col = (i & 15) * 4;
            *(float4*)&Ks[row][col] = *(const float4*)(Kb + (size_t)(t0 + row) * FEATS + col);
            *(float4*)&Vs[row][col] = *(const float4*)(Vb + (size_t)(t0 + row) * FEATS + col);
        }
        __syncthreads();
        #pragma unroll
        for (int tt = 0; tt < 32; tt++) {
            float4 kv = *(const float4*)&Ks[tt][ti * 4];
            float4 vv = *(const float4*)&Vs[tt][tj * 4];
            float ka[4] = {kv.x, kv.y, kv.z, kv.w};
            float va[4] = {vv.x, vv.y, vv.z, vv.w};
            #pragma unroll
            for (int a = 0; a < 4; a++)
                #pragma unroll
                for (int c = 0; c < 4; c++)
                    acc[a][c] = fmaf(ka[a], va[c], acc[a][c]);
        }
        __syncthreads();
    }

    float* out = g_Mpart + ((size_t)s * 64 + bh) * HDIM * HDIM;
    #pragma unroll
    for (int a = 0; a < 4; a++)
        #pragma unroll
        for (int c = 0; c < 4; c++)
            out[(ti * 4 + a) * HDIM + (tj * 4 + c)] = acc[a][c];
}

__global__ void reduce_m_kernel()
{
    int i = blockIdx.x * blockDim.x + threadIdx.x;
    const int per = 64 * HDIM * HDIM;
    if (i >= per) return;
    float sum = 0.0f;
    #pragma unroll
    for (int p = 0; p < NSPLIT; p++) sum += g_Mpart[(size_t)p * per + i];
    g_M[i] = sum;
}

// ---------------------------------------------------------------------------
// O = Q @ M / n^sigmoid(m_h), written as fp16 for the final GEMM.
// ---------------------------------------------------------------------------
__global__ void qm_kernel(const float* __restrict__ Qbuf, const float* __restrict__ m)
{
    const int bh = blockIdx.y;
    const int b  = bh >> 4, h = bh & 15;
    const int t0 = blockIdx.x * 32;

    __shared__ float Ms[64][64];
    __shared__ float Qs[32][68];

    const int tid = threadIdx.x;

    float sig   = 1.0f / (1.0f + expf(-m[h]));
    float inv_s = powf((float)SEQ, -sig);

    const float* Mp = g_M + (size_t)bh * HDIM * HDIM;
    for (int i = tid; i < HDIM * HDIM; i += 256)
        ((float*)Ms)[(i >> 6) * 64 + (i & 63)] = Mp[i] * inv_s;

    const float* Qb = Qbuf + (size_t)(b * SEQ + t0) * FEATS + h * HDIM;
    #pragma unroll
    for (int l2 = 0; l2 < 2; l2++) {
        int i   = tid + l2 * 256;
        int row = i >> 4;
        int col = (i & 15) * 4;
        *(float4*)&Qs[row][col] = *(const float4*)(Qb + (size_t)row * FEATS + col);
    }
    __syncthreads();

    const int tl = tid >> 3;
    const int j0 = (tid & 7) * 8;

    float acc[8];
    #pragma unroll
    for (int j = 0; j < 8; j++) acc[j] = 0.0f;

    #pragma unroll
    for (int i = 0; i < HDIM; i++) {
        float q  = Qs[tl][i];
        float4 m0 = *(const float4*)&Ms[i][j0];
        float4 m1 = *(const float4*)&Ms[i][j0 + 4];
        acc[0] = fmaf(q, m0.x, acc[0]);
        acc[1] = fmaf(q, m0.y, acc[1]);
        acc[2] = fmaf(q, m0.z, acc[2]);
        acc[3] = fmaf(q, m0.w, acc[3]);
        acc[4] = fmaf(q, m1.x, acc[4]);
        acc[5] = fmaf(q, m1.y, acc[5]);
        acc[6] = fmaf(q, m1.z, acc[6]);
        acc[7] = fmaf(q, m1.w, acc[7]);
    }

    // convert to fp16 and store packed (8 halves = 16B)
    uint32_t hv[4];
    #pragma unroll
    for (int q4 = 0; q4 < 4; q4++) {
        __half2 p = __floats2half2_rn(acc[q4 * 2], acc[q4 * 2 + 1]);
        hv[q4] = *(uint32_t*)&p;
    }
    size_t off = (size_t)(b * SEQ + t0 + tl) * FEATS + h * HDIM + j0;
    *(uint4*)((char*)g_Ox + off * 2) = make_uint4(hv[0], hv[1], hv[2], hv[3]);
}

// ---------------------------------------------------------------------------
// Launch
// ---------------------------------------------------------------------------
extern "C" void kernel_launch(void* const* d_in, const int* in_sizes, int n_in,
                              void* d_out, int out_size)
{
    const float* x  = (const float*)d_in[0];
    const float* Wq = (const float*)d_in[1];
    const float* bq = (const float*)d_in[2];
    const float* Wk = (const float*)d_in[3];
    const float* bk = (const float*)d_in[4];
    const float* Wv = (const float*)d_in[5];
    const float* bv = (const float*)d_in[6];
    const float* Wo = (const float*)d_in[7];
    const float* bo = (const float*)d_in[8];
    const float* m  = (const float*)d_in[9];
    float* out = (float*)d_out;

    void *pQ, *pK, *pV, *pWH, *pWL, *pXh, *pOx;
    cudaGetSymbolAddress(&pQ, g_Q);
    cudaGetSymbolAddress(&pK, g_K);
    cudaGetSymbolAddress(&pV, g_V);
    cudaGetSymbolAddress(&pWH, g_WtH);
    cudaGetSymbolAddress(&pWL, g_WtL);
    cudaGetSymbolAddress(&pXh, g_Xh);
    cudaGetSymbolAddress(&pOx, g_Ox);
    float* Qb = (float*)pQ;
    float* Kb = (float*)pK;
    float* Vb = (float*)pV;
    const __half* WH = (const __half*)pWH;
    const __half* WL = (const __half*)pWL;
    const __half* Xh = (const __half*)pXh;
    const __half* Ox = (const __half*)pOx;
    const size_t FF = (size_t)FEATS * FEATS;

    cudaFuncSetAttribute(gemm_kernel, cudaFuncAttributeMaxDynamicSharedMemorySize,
                         GEMM_SMEM);

    // 1. Convert inputs: W -> fp16 hi/lo (scaled), x -> fp16
    prep_w_kernel<<<dim3(32, 32, 4), 256>>>(Wq, Wk, Wv, Wo);
    prep_x_kernel<<<TOKENS * FEATS / 4 / 256, 256>>>(x);

    // 2. Projections via fp16 2-pass mma.sync (Q/K with fused per-head L2 norm)
    dim3 gGemm(FEATS / 128, TOKENS / 128);   // (8, 64)
    gemm_kernel<<<gGemm, 256, GEMM_SMEM>>>(Xh, WH + 0 * FF, WL + 0 * FF, bq, Qb, 1);
    gemm_kernel<<<gGemm, 256, GEMM_SMEM>>>(Xh, WH + 1 * FF, WL + 1 * FF, bk, Kb, 1);
    gemm_kernel<<<gGemm, 256, GEMM_SMEM>>>(Xh, WH + 2 * FF, WL + 2 * FF, bv, Vb, 0);

    // 3. Linear attention: M = K^T V, O = Q M / n^sigmoid(m)
    ktv_kernel<<<dim3(64, NSPLIT), 256>>>(Kb, Vb);
    reduce_m_kernel<<<(64 * HDIM * HDIM + 255) / 256, 256>>>();
    qm_kernel<<<dim3(SEQ / 32, 64), 256>>>(Qb, m);

    // 4. Output projection
    gemm_kernel<<<gGemm, 256, GEMM_SMEM>>>(Ox, WH + 3 * FF, WL + 3 * FF, bo, out, 0);
}

// round 7
// speedup vs baseline: 4.5784x; 1.4998x over previous
#include <cuda_runtime.h>
#include <cuda_bf16.h>
#include <cuda_fp16.h>
#include <math.h>
#include <stdint.h>

// Problem constants
#define BATCH 4
#define SEQ   2048
#define FEATS 1024
#define HEADS 16
#define HDIM  64
#define TOKENS (BATCH * SEQ)          // 8192
#define NSPLIT 8

// ---------------------------------------------------------------------------
// Scratch (device globals; no allocation allowed)
// ---------------------------------------------------------------------------
__device__ float g_Q[TOKENS * FEATS];
__device__ float g_K[TOKENS * FEATS];
__device__ float g_V[TOKENS * FEATS];
__device__ float g_Mpart[NSPLIT * 64 * HDIM * HDIM];
__device__ float g_M[64 * HDIM * HDIM];
__device__ __half g_Wt[4u * FEATS * FEATS];    // transposed weights fp16 [4][N][K]
__device__ __half g_Xh[TOKENS * FEATS];        // x as fp16
__device__ __half g_Ox[TOKENS * FEATS];        // attention out as fp16

// ---------------------------------------------------------------------------
// PTX helpers (sm_100-safe: mma.sync + ldmatrix + cp.async only)
// ---------------------------------------------------------------------------
__device__ __forceinline__ uint32_t smem_u32(const void* p) {
    uint32_t a;
    asm("{ .reg .u64 t; cvta.to.shared.u64 t, %1; cvt.u32.u64 %0, t; }"
        : "=r"(a) : "l"(p));
    return a;
}

#define CP16(dst, src) \
    asm volatile("cp.async.cg.shared.global [%0], [%1], 16;" \
                 :: "r"(dst), "l"(src) : "memory")
#define CP_COMMIT() asm volatile("cp.async.commit_group;" ::: "memory")
#define CP_WAIT1()  asm volatile("cp.async.wait_group 1;" ::: "memory")
#define CP_WAIT0()  asm volatile("cp.async.wait_group 0;" ::: "memory")

#define LDSM_X4(r0, r1, r2, r3, addr) \
    asm volatile("ldmatrix.sync.aligned.m8n8.x4.shared.b16 {%0,%1,%2,%3}, [%4];" \
                 : "=r"(r0), "=r"(r1), "=r"(r2), "=r"(r3) : "r"(addr))

#define MMA_F16(d, a, b0, b1) \
    asm volatile("mma.sync.aligned.m16n8k16.row.col.f32.f16.f16.f32 " \
                 "{%0,%1,%2,%3}, {%4,%5,%6,%7}, {%8,%9}, {%0,%1,%2,%3};" \
                 : "+f"((d)[0]), "+f"((d)[1]), "+f"((d)[2]), "+f"((d)[3]) \
                 : "r"((a)[0]), "r"((a)[1]), "r"((a)[2]), "r"((a)[3]), \
                   "r"(b0), "r"(b1))

// ---------------------------------------------------------------------------
// prep_w: W[K,N] fp32 -> Wt[N,K] fp16  (4 weight matrices)
// ---------------------------------------------------------------------------
__global__ void prep_w_kernel(const float* __restrict__ W0, const float* __restrict__ W1,
                              const float* __restrict__ W2, const float* __restrict__ W3)
{
    __shared__ float t[32][33];
    const int z = blockIdx.z;
    const float* W = (z == 0) ? W0 : (z == 1) ? W1 : (z == 2) ? W2 : W3;
    __half* Hp = g_Wt + (size_t)z * FEATS * FEATS;
    const int n0 = blockIdx.x * 32, k0 = blockIdx.y * 32;
    const int tid = threadIdx.x;
    const int a = tid & 31, bq = tid >> 5;
    #pragma unroll
    for (int it = 0; it < 4; it++) {
        int kk = bq + it * 8;
        t[kk][a] = W[(size_t)(k0 + kk) * FEATS + n0 + a];
    }
    __syncthreads();
    #pragma unroll
    for (int it = 0; it < 4; it++) {
        int nn = bq + it * 8;
        Hp[(size_t)(n0 + nn) * FEATS + k0 + a] = __float2half_rn(t[a][nn]);
    }
}

// ---------------------------------------------------------------------------
// prep_x: x fp32 -> fp16
// ---------------------------------------------------------------------------
__global__ void prep_x_kernel(const float* __restrict__ X)
{
    size_t i = (size_t)blockIdx.x * 256 + threadIdx.x;   // float4 index
    float4 v = ((const float4*)X)[i];
    uint2 hp;
    __half2 p0 = __floats2half2_rn(v.x, v.y);
    __half2 p1 = __floats2half2_rn(v.z, v.w);
    hp.x = *(uint32_t*)&p0;
    hp.y = *(uint32_t*)&p1;
    ((uint2*)g_Xh)[i] = hp;
}

// ---------------------------------------------------------------------------
// fp16 GEMM:  C[8192, NW] = A @ B^T + bias  (B rows = output features)
// Tile 128x128x64, 8 warps (4x2), warp tile 32x64, 3-stage cp.async pipeline.
// fused=1: B spans 3 matrices (QKV, NW=3072); per-tile z selects output/bias,
//          z<2 gets fused per-head L2 norm.  fused=0: single matrix (NW=1024).
// ---------------------------------------------------------------------------
#define GBK 64
#define NCHUNK (FEATS / GBK)           // 16
#define TILE_B 16384                   // one 128x64 fp16 tile
#define STAGE_B (2 * TILE_B)           // 32768 (A + B)
#define OFF_A  0
#define OFF_B  TILE_B
#define GEMM_SMEM (3 * STAGE_B)        // 98304

__device__ __forceinline__ void gemm_issue(uint32_t st, int tid,
    const __half* __restrict__ A, const __half* __restrict__ B,
    int m0, int gn0, int k0)
{
    const uint32_t sa = st + OFF_A;
    const uint32_t sb2 = st + OFF_B;
    #pragma unroll
    for (int t = 0; t < 4; t++) {
        const int i  = tid + t * 256;   // 0..1023
        const int r  = i >> 3;          // 0..127
        const int ch = i & 7;           // 16B chunk within 128B row
        const uint32_t d = (uint32_t)(r * 128 + ((ch ^ (r & 7)) << 4));
        CP16(sa  + d, A + (size_t)(m0 + r) * FEATS + k0 + ch * 8);
        CP16(sb2 + d, B + (size_t)(gn0 + r) * FEATS + k0 + ch * 8);
    }
    CP_COMMIT();
}

__global__ __launch_bounds__(256, 2)
void gemm_kernel(const __half* __restrict__ A, const __half* __restrict__ B,
                 float* __restrict__ C0, float* __restrict__ C1, float* __restrict__ C2,
                 const float* __restrict__ b0, const float* __restrict__ b1,
                 const float* __restrict__ b2, int fused)
{
    extern __shared__ char smem[];
    const uint32_t sb = smem_u32(smem);
    const int tid  = threadIdx.x;
    const int lane = tid & 31;
    const int warp = tid >> 5;
    const int wm   = warp & 3;         // 0..3 (M)
    const int wn   = warp >> 2;        // 0..1 (N)
    const int m0  = blockIdx.y * 128;
    const int gn0 = blockIdx.x * 128;  // global row in B (0..3071 fused)
    const int z   = fused ? (gn0 >> 10) : 0;
    const int n0  = fused ? (gn0 & 1023) : gn0;   // local output column base
    float* C = (z == 0) ? C0 : (z == 1) ? C1 : C2;
    const float* bias = (z == 0) ? b0 : (z == 1) ? b1 : b2;
    const int do_norm = fused && (z < 2);

    float acc[2][8][4];
    #pragma unroll
    for (int a = 0; a < 2; a++)
        #pragma unroll
        for (int j = 0; j < 8; j++)
            #pragma unroll
            for (int k = 0; k < 4; k++) acc[a][j][k] = 0.0f;

    // prologue: stages 0, 1
    gemm_issue(sb + 0 * STAGE_B, tid, A, B, m0, gn0, 0);
    gemm_issue(sb + 1 * STAGE_B, tid, A, B, m0, gn0, GBK);

    for (int c = 0; c < NCHUNK; c++) {
        if (c + 2 < NCHUNK) CP_WAIT1(); else CP_WAIT0();
        __syncthreads();
        if (c + 2 < NCHUNK)
            gemm_issue(sb + ((c + 2) % 3) * STAGE_B, tid, A, B, m0, gn0,
                       (c + 2) * GBK);

        const uint32_t st = sb + (c % 3) * STAGE_B;
        #pragma unroll
        for (int s = 0; s < 4; s++) {     // k16 steps within 64-chunk
            const int chl = s * 2 + (lane >> 4);
            uint32_t ah[2][4];
            #pragma unroll
            for (int a = 0; a < 2; a++) {
                int row = wm * 32 + a * 16 + (lane & 15);
                uint32_t off = (uint32_t)(row * 128 + ((chl ^ (row & 7)) << 4));
                LDSM_X4(ah[a][0], ah[a][1], ah[a][2], ah[a][3], st + OFF_A + off);
            }
            uint32_t bh[4][4];
            #pragma unroll
            for (int p = 0; p < 4; p++) {
                int row = wn * 64 + p * 16 + (lane & 15);
                uint32_t off = (uint32_t)(row * 128 + ((chl ^ (row & 7)) << 4));
                LDSM_X4(bh[p][0], bh[p][1], bh[p][2], bh[p][3], st + OFF_B + off);
            }
            #pragma unroll
            for (int a = 0; a < 2; a++)
                #pragma unroll
                for (int j = 0; j < 8; j++) {
                    const int p = j >> 1, q = j & 1;
                    MMA_F16(acc[a][j], ah[a], bh[p][q], bh[p][q + 2]);
                }
        }
    }

    // ---- epilogue: +bias, optional per-head L2 norm (warp n-span = 1 head) ----
    float2 bv[8];
    #pragma unroll
    for (int j = 0; j < 8; j++)
        bv[j] = *(const float2*)&bias[n0 + wn * 64 + j * 8 + (lane & 3) * 2];
    #pragma unroll
    for (int a = 0; a < 2; a++)
        #pragma unroll
        for (int j = 0; j < 8; j++) {
            acc[a][j][0] += bv[j].x;
            acc[a][j][1] += bv[j].y;
            acc[a][j][2] += bv[j].x;
            acc[a][j][3] += bv[j].y;
        }

    float inv[2][2] = {{1.0f, 1.0f}, {1.0f, 1.0f}};
    if (do_norm) {
        #pragma unroll
        for (int a = 0; a < 2; a++) {
            float s0 = 0.0f, s1 = 0.0f;
            #pragma unroll
            for (int j = 0; j < 8; j++) {
                s0 += acc[a][j][0] * acc[a][j][0] + acc[a][j][1] * acc[a][j][1];
                s1 += acc[a][j][2] * acc[a][j][2] + acc[a][j][3] * acc[a][j][3];
            }
            s0 += __shfl_xor_sync(0xffffffff, s0, 1);
            s0 += __shfl_xor_sync(0xffffffff, s0, 2);
            s1 += __shfl_xor_sync(0xffffffff, s1, 1);
            s1 += __shfl_xor_sync(0xffffffff, s1, 2);
            inv[a][0] = 1.0f / fmaxf(sqrtf(s0), 1e-12f);
            inv[a][1] = 1.0f / fmaxf(sqrtf(s1), 1e-12f);
        }
    }

    #pragma unroll
    for (int a = 0; a < 2; a++) {
        int row = m0 + wm * 32 + a * 16 + (lane >> 2);
        #pragma unroll
        for (int j = 0; j < 8; j++) {
            int col = n0 + wn * 64 + j * 8 + (lane & 3) * 2;
            *(float2*)&C[(size_t)row * FEATS + col] =
                make_float2(acc[a][j][0] * inv[a][0], acc[a][j][1] * inv[a][0]);
            *(float2*)&C[(size_t)(row + 8) * FEATS + col] =
                make_float2(acc[a][j][2] * inv[a][1], acc[a][j][3] * inv[a][1]);
        }
    }
}

// ---------------------------------------------------------------------------
// KtV partials
// ---------------------------------------------------------------------------
__global__ void ktv_kernel(const float* __restrict__ Kbuf, const float* __restrict__ Vbuf)
{
    const int bh = blockIdx.x;
    const int s  = blockIdx.y;
    const int b  = bh >> 4, h = bh & 15;
    const float* Kb = Kbuf + (size_t)b * SEQ * FEATS + h * HDIM;
    const float* Vb = Vbuf + (size_t)b * SEQ * FEATS + h * HDIM;

    __shared__ float Ks[32][64];
    __shared__ float Vs[32][64];

    const int tid = threadIdx.x;
    const int ti  = tid >> 4;
    const int tj  = tid & 15;

    float acc[4][4];
    #pragma unroll
    for (int a = 0; a < 4; a++)
        #pragma unroll
        for (int c = 0; c < 4; c++) acc[a][c] = 0.0f;

    const int tokens_per_split = SEQ / NSPLIT;
    for (int t0 = s * tokens_per_split; t0 < (s + 1) * tokens_per_split; t0 += 32) {
        #pragma unroll
        for (int l2 = 0; l2 < 2; l2++) {
            int i   = tid + l2 * 256;
            int row = i >> 4;
            int col = (i & 15) * 4;
            *(float4*)&Ks[row][col] = *(const float4*)(Kb + (size_t)(t0 + row) * FEATS + col);
            *(float4*)&Vs[row][col] = *(const float4*)(Vb + (size_t)(t0 + row) * FEATS + col);
        }
        __syncthreads();
        #pragma unroll
        for (int tt = 0; tt < 32; tt++) {
            float4 kv = *(const float4*)&Ks[tt][ti * 4];
            float4 vv = *(const float4*)&Vs[tt][tj * 4];
            float ka[4] = {kv.x, kv.y, kv.z, kv.w};
            float va[4] = {vv.x, vv.y, vv.z, vv.w};
            #pragma unroll
            for (int a = 0; a < 4; a++)
                #pragma unroll
                for (int c = 0; c < 4; c++)
                    acc[a][c] = fmaf(ka[a], va[c], acc[a][c]);
        }
        __syncthreads();
    }

    float* out = g_Mpart + ((size_t)s * 64 + bh) * HDIM * HDIM;
    #pragma unroll
    for (int a = 0; a < 4; a++)
        #pragma unroll
        for (int c = 0; c < 4; c++)
            out[(ti * 4 + a) * HDIM + (tj * 4 + c)] = acc[a][c];
}

__global__ void reduce_m_kernel()
{
    int i = blockIdx.x * blockDim.x + threadIdx.x;
    const int per = 64 * HDIM * HDIM;
    if (i >= per) return;
    float sum = 0.0f;
    #pragma unroll
    for (int p = 0; p < NSPLIT; p++) sum += g_Mpart[(size_t)p * per + i];
    g_M[i] = sum;
}

// ---------------------------------------------------------------------------
// O = Q @ M / n^sigmoid(m_h), written as fp16 for the final GEMM.
// ---------------------------------------------------------------------------
__global__ void qm_kernel(const float* __restrict__ Qbuf, const float* __restrict__ m)
{
    const int bh = blockIdx.y;
    const int b  = bh >> 4, h = bh & 15;
    const int t0 = blockIdx.x * 32;

    __shared__ float Ms[64][64];
    __shared__ float Qs[32][68];

    const int tid = threadIdx.x;

    float sig   = 1.0f / (1.0f + expf(-m[h]));
    float inv_s = powf((float)SEQ, -sig);

    const float* Mp = g_M + (size_t)bh * HDIM * HDIM;
    for (int i = tid; i < HDIM * HDIM; i += 256)
        ((float*)Ms)[(i >> 6) * 64 + (i & 63)] = Mp[i] * inv_s;

    const float* Qb = Qbuf + (size_t)(b * SEQ + t0) * FEATS + h * HDIM;
    #pragma unroll
    for (int l2 = 0; l2 < 2; l2++) {
        int i   = tid + l2 * 256;
        int row = i >> 4;
        int col = (i & 15) * 4;
        *(float4*)&Qs[row][col] = *(const float4*)(Qb + (size_t)row * FEATS + col);
    }
    __syncthreads();

    const int tl = tid >> 3;
    const int j0 = (tid & 7) * 8;

    float acc[8];
    #pragma unroll
    for (int j = 0; j < 8; j++) acc[j] = 0.0f;

    #pragma unroll
    for (int i = 0; i < HDIM; i++) {
        float q  = Qs[tl][i];
        float4 m0 = *(const float4*)&Ms[i][j0];
        float4 m1 = *(const float4*)&Ms[i][j0 + 4];
        acc[0] = fmaf(q, m0.x, acc[0]);
        acc[1] = fmaf(q, m0.y, acc[1]);
        acc[2] = fmaf(q, m0.z, acc[2]);
        acc[3] = fmaf(q, m0.w, acc[3]);
        acc[4] = fmaf(q, m1.x, acc[4]);
        acc[5] = fmaf(q, m1.y, acc[5]);
        acc[6] = fmaf(q, m1.z, acc[6]);
        acc[7] = fmaf(q, m1.w, acc[7]);
    }

    // convert to fp16 and store packed (8 halves = 16B)
    uint32_t hv[4];
    #pragma unroll
    for (int q4 = 0; q4 < 4; q4++) {
        __half2 p = __floats2half2_rn(acc[q4 * 2], acc[q4 * 2 + 1]);
        hv[q4] = *(uint32_t*)&p;
    }
    size_t off = (size_t)(b * SEQ + t0 + tl) * FEATS + h * HDIM + j0;
    *(uint4*)((char*)g_Ox + off * 2) = make_uint4(hv[0], hv[1], hv[2], hv[3]);
}

// ---------------------------------------------------------------------------
// Launch
// ---------------------------------------------------------------------------
extern "C" void kernel_launch(void* const* d_in, const int* in_sizes, int n_in,
                              void* d_out, int out_size)
{
    const float* x  = (const float*)d_in[0];
    const float* Wq = (const float*)d_in[1];
    const float* bq = (const float*)d_in[2];
    const float* Wk = (const float*)d_in[3];
    const float* bk = (const float*)d_in[4];
    const float* Wv = (const float*)d_in[5];
    const float* bv = (const float*)d_in[6];
    const float* Wo = (const float*)d_in[7];
    const float* bo = (const float*)d_in[8];
    const float* m  = (const float*)d_in[9];
    float* out = (float*)d_out;

    void *pQ, *pK, *pV, *pW, *pXh, *pOx;
    cudaGetSymbolAddress(&pQ, g_Q);
    cudaGetSymbolAddress(&pK, g_K);
    cudaGetSymbolAddress(&pV, g_V);
    cudaGetSymbolAddress(&pW, g_Wt);
    cudaGetSymbolAddress(&pXh, g_Xh);
    cudaGetSymbolAddress(&pOx, g_Ox);
    float* Qb = (float*)pQ;
    float* Kb = (float*)pK;
    float* Vb = (float*)pV;
    const __half* Wt = (const __half*)pW;
    const __half* Xh = (const __half*)pXh;
    const __half* Ox = (const __half*)pOx;
    const size_t FF = (size_t)FEATS * FEATS;

    cudaFuncSetAttribute(gemm_kernel, cudaFuncAttributeMaxDynamicSharedMemorySize,
                         GEMM_SMEM);

    // 1. Convert inputs: W -> fp16 transposed, x -> fp16
    prep_w_kernel<<<dim3(32, 32, 4), 256>>>(Wq, Wk, Wv, Wo);
    prep_x_kernel<<<TOKENS * FEATS / 4 / 256, 256>>>(x);

    // 2. Fused QKV projection (single launch, N=3072; Q/K get fused L2 norm)
    dim3 gQKV(3 * FEATS / 128, TOKENS / 128);   // (24, 64)
    gemm_kernel<<<gQKV, 256, GEMM_SMEM>>>(Xh, Wt, Qb, Kb, Vb, bq, bk, bv, 1);

    // 3. Linear attention: M = K^T V, O = Q M / n^sigmoid(m)
    ktv_kernel<<<dim3(64, NSPLIT), 256>>>(Kb, Vb);
    reduce_m_kernel<<<(64 * HDIM * HDIM + 255) / 256, 256>>>();
    qm_kernel<<<dim3(SEQ / 32, 64), 256>>>(Qb, m);

    // 4. Output projection
    dim3 gOut(FEATS / 128, TOKENS / 128);       // (8, 64)
    gemm_kernel<<<gOut, 256, GEMM_SMEM>>>(Ox, Wt + 3 * FF, out, out, out,
                                          bo, bo, bo, 0);
}